// round 11
// baseline (speedup 1.0000x reference)
#include <cuda_runtime.h>
#include <math.h>

#define NMAX 100000
#define EMAX 1600000
#define BN_EPS 1e-5f

// ---------------- scratch (static device globals; no allocations) ----------------
__device__ int    g_deg[NMAX];
__device__ int    g_off[NMAX + 1];
__device__ int    g_cur[NMAX];
__device__ int    g_csr[EMAX];
__device__ int    g_bsum[256];
__device__ float  g_dinv[NMAX];
__device__ float  g_hs[NMAX * 64];    // pre-scaled linear output (x_s = dinv * (xW^T + b))
__device__ float  g_agg[NMAX * 64];   // aggregated GCN-layer output
__device__ double g_csum[64];
__device__ double g_csq[64];
__device__ float  g_sc[64];           // BN scale  (g * rsqrt(var+eps))
__device__ float  g_sh[64];           // BN shift  (beta - mu * scale)

// ---------------- preprocessing ----------------
__global__ void zero_deg(int n) {
    int i = blockIdx.x * blockDim.x + threadIdx.x;
    if (i < n) g_deg[i] = 0;
}

__global__ void count_deg(const int* __restrict__ dst, int e) {
    int i = blockIdx.x * blockDim.x + threadIdx.x;
    if (i < e) atomicAdd(&g_deg[dst[i]], 1);
}

__global__ void scan_reduce(int n) {
    __shared__ int s[1024];
    int i = blockIdx.x * 1024 + threadIdx.x;
    s[threadIdx.x] = (i < n) ? g_deg[i] : 0;
    __syncthreads();
    for (int d = 512; d > 0; d >>= 1) {
        if (threadIdx.x < d) s[threadIdx.x] += s[threadIdx.x + d];
        __syncthreads();
    }
    if (threadIdx.x == 0) g_bsum[blockIdx.x] = s[0];
}

__global__ void scan_bsums(int nb, int n) {
    if (threadIdx.x == 0) {
        int run = 0;
        for (int b = 0; b < nb; b++) { int t = g_bsum[b]; g_bsum[b] = run; run += t; }
        g_off[n] = run;
    }
}

__global__ void scan_final(int n) {
    __shared__ int s[1024];
    int tid = threadIdx.x;
    int i = blockIdx.x * 1024 + tid;
    int v = (i < n) ? g_deg[i] : 0;
    s[tid] = v;
    __syncthreads();
    for (int d = 1; d < 1024; d <<= 1) {
        int t = (tid >= d) ? s[tid - d] : 0;
        __syncthreads();
        s[tid] += t;
        __syncthreads();
    }
    if (i < n) {
        int ex = g_bsum[blockIdx.x] + s[tid] - v;   // exclusive prefix
        g_off[i] = ex;
        g_cur[i] = ex;
    }
}

__global__ void fill_csr(const int* __restrict__ src, const int* __restrict__ dst, int e) {
    int i = blockIdx.x * blockDim.x + threadIdx.x;
    if (i < e) {
        int p = atomicAdd(&g_cur[dst[i]], 1);
        g_csr[p] = src[i];
    }
}

__global__ void compute_dinv(int n) {
    int i = blockIdx.x * blockDim.x + threadIdx.x;
    if (i < n) g_dinv[i] = rsqrtf((float)(g_deg[i] + 1));   // +1 self-loop
}

__global__ void zero_stats() {
    int t = threadIdx.x;
    if (t < 64) { g_csum[t] = 0.0; g_csq[t] = 0.0; }
}

__global__ void bn_finalize(const float* __restrict__ g, const float* __restrict__ be, float invn) {
    int t = threadIdx.x;
    if (t < 64) {
        double mu  = g_csum[t] * (double)invn;
        double var = g_csq[t] * (double)invn - mu * mu;
        float rs = (float)(1.0 / sqrt(var + (double)BN_EPS));
        float sc = g[t] * rs;
        g_sc[t] = sc;
        g_sh[t] = be[t] - (float)mu * sc;
    }
}

// ---------------- linear: h_s[r] = dinv[r] * (act(in[r]) @ W^T + b) ----------------
// thread-per-row, 64 accumulators in registers, W staged in smem (broadcast reads).
template <int K, bool BN>
__global__ void __launch_bounds__(128) linear_kernel(
    const float* __restrict__ in, const float* __restrict__ W,
    const float* __restrict__ b, float* __restrict__ out, int n)
{
    __shared__ float Ws[64 * K];
    __shared__ float sb[64];
    __shared__ float ssc[64];
    __shared__ float ssh[64];
    int tid = threadIdx.x;

    const float4* W4  = (const float4*)W;
    float4*       Ws4 = (float4*)Ws;
    for (int idx = tid; idx < K * 16; idx += 128) Ws4[idx] = W4[idx];
    if (tid < 64) {
        sb[tid] = b[tid];
        if (BN) { ssc[tid] = g_sc[tid]; ssh[tid] = g_sh[tid]; }
    }
    __syncthreads();

    int r = blockIdx.x * 128 + tid;
    if (r >= n) return;

    float acc[64];
#pragma unroll
    for (int o = 0; o < 64; o++) acc[o] = sb[o];

    const float4* xr4 = (const float4*)(in + (long)r * K);
#pragma unroll 1
    for (int kb = 0; kb < K; kb += 8) {
        float xr[8];
        float4 v0 = xr4[kb / 4];
        float4 v1 = xr4[kb / 4 + 1];
        xr[0] = v0.x; xr[1] = v0.y; xr[2] = v0.z; xr[3] = v0.w;
        xr[4] = v1.x; xr[5] = v1.y; xr[6] = v1.z; xr[7] = v1.w;
        if (BN) {
#pragma unroll
            for (int kk = 0; kk < 8; kk++)
                xr[kk] = fmaxf(fmaf(xr[kk], ssc[kb + kk], ssh[kb + kk]), 0.0f);
        }
#pragma unroll
        for (int o = 0; o < 64; o++) {
#pragma unroll
            for (int kk = 0; kk < 8; kk++)
                acc[o] = fmaf(xr[kk], Ws[o * K + kb + kk], acc[o]);
        }
    }

    float di = g_dinv[r];
    float4* o4 = (float4*)(out + (long)r * 64);
#pragma unroll
    for (int o = 0; o < 16; o++) {
        float4 v;
        v.x = acc[4 * o + 0] * di;
        v.y = acc[4 * o + 1] * di;
        v.z = acc[4 * o + 2] * di;
        v.w = acc[4 * o + 3] * di;
        o4[o] = v;
    }
}

// ---------------- aggregation: out[i] = dinv[i]*(hs[i] + sum_{src in N(i)} hs[src]) --------
// warp per node; lane owns features {2*lane, 2*lane+1}. 4 independent accumulator
// chains in the gather loop guarantee MLP>=4 per warp. MODE 0: + BN column stats.
// MODE 2: + fused log_softmax, writes final output.
template <int MODE>
__global__ void __launch_bounds__(512) agg_kernel(
    const float* __restrict__ hs, float* __restrict__ out, int n)
{
    constexpr bool STATS = (MODE == 0);
    constexpr bool SMAX  = (MODE == 2);
    __shared__ float ssum[64];
    __shared__ float ssq[64];
    int tid = threadIdx.x;
    if (STATS) {
        if (tid < 64) { ssum[tid] = 0.0f; ssq[tid] = 0.0f; }
        __syncthreads();
    }
    int node = (blockIdx.x * 512 + tid) >> 5;
    int lane = tid & 31;
    if (node < n) {
        const float2* h2 = (const float2*)hs;
        float2 a0 = h2[(long)node * 32 + lane];        // self-loop term
        float2 a1 = make_float2(0.0f, 0.0f);
        float2 a2 = make_float2(0.0f, 0.0f);
        float2 a3 = make_float2(0.0f, 0.0f);
        int s0 = g_off[node], s1 = g_off[node + 1];
        for (int base = s0; base < s1; base += 32) {
            int j = base + lane;
            int se = (j < s1) ? g_csr[j] : 0;
            int cnt = min(32, s1 - base);
            int t = 0;
            for (; t + 4 <= cnt; t += 4) {
                int i0 = __shfl_sync(0xffffffffu, se, t);
                int i1 = __shfl_sync(0xffffffffu, se, t + 1);
                int i2 = __shfl_sync(0xffffffffu, se, t + 2);
                int i3 = __shfl_sync(0xffffffffu, se, t + 3);
                float2 v0 = h2[(long)i0 * 32 + lane];
                float2 v1 = h2[(long)i1 * 32 + lane];
                float2 v2 = h2[(long)i2 * 32 + lane];
                float2 v3 = h2[(long)i3 * 32 + lane];
                a0.x += v0.x; a0.y += v0.y;
                a1.x += v1.x; a1.y += v1.y;
                a2.x += v2.x; a2.y += v2.y;
                a3.x += v3.x; a3.y += v3.y;
            }
            for (; t < cnt; t++) {
                int s = __shfl_sync(0xffffffffu, se, t);
                float2 v = h2[(long)s * 32 + lane];
                a0.x += v.x; a0.y += v.y;
            }
        }
        float2 acc;
        acc.x = (a0.x + a1.x) + (a2.x + a3.x);
        acc.y = (a0.y + a1.y) + (a2.y + a3.y);
        float di = g_dinv[node];
        acc.x *= di; acc.y *= di;
        if (SMAX) {
            float m = fmaxf(acc.x, acc.y);
#pragma unroll
            for (int o = 16; o > 0; o >>= 1) m = fmaxf(m, __shfl_xor_sync(0xffffffffu, m, o));
            float sum = expf(acc.x - m) + expf(acc.y - m);
#pragma unroll
            for (int o = 16; o > 0; o >>= 1) sum += __shfl_xor_sync(0xffffffffu, sum, o);
            float l = m + logf(sum);
            float2 r; r.x = acc.x - l; r.y = acc.y - l;
            ((float2*)out)[(long)node * 32 + lane] = r;
        } else {
            ((float2*)out)[(long)node * 32 + lane] = acc;
            if (STATS) {
                atomicAdd(&ssum[2 * lane + 0], acc.x);
                atomicAdd(&ssum[2 * lane + 1], acc.y);
                atomicAdd(&ssq[2 * lane + 0], acc.x * acc.x);
                atomicAdd(&ssq[2 * lane + 1], acc.y * acc.y);
            }
        }
    }
    if (STATS) {
        __syncthreads();
        if (tid < 64) {
            atomicAdd(&g_csum[tid], (double)ssum[tid]);
            atomicAdd(&g_csq[tid],  (double)ssq[tid]);
        }
    }
}

// ---------------- launch ----------------
extern "C" void kernel_launch(void* const* d_in, const int* in_sizes, int n_in,
                              void* d_out, int out_size)
{
    const float* x   = (const float*)d_in[0];
    const int*   ei  = (const int*)  d_in[1];
    const float* W1  = (const float*)d_in[2];
    const float* b1  = (const float*)d_in[3];
    const float* g1  = (const float*)d_in[4];
    const float* be1 = (const float*)d_in[5];
    const float* W2  = (const float*)d_in[6];
    const float* b2  = (const float*)d_in[7];
    const float* g2  = (const float*)d_in[8];
    const float* be2 = (const float*)d_in[9];
    const float* W3  = (const float*)d_in[10];
    const float* b3  = (const float*)d_in[11];
    float* out = (float*)d_out;

    int n = in_sizes[0] / 128;
    int e = in_sizes[1] / 2;
    const int* src = ei;
    const int* dst = ei + e;

    float* hs;  cudaGetSymbolAddress((void**)&hs,  g_hs);
    float* agg; cudaGetSymbolAddress((void**)&agg, g_agg);

    int nb = (n + 1023) / 1024;
    int eb = (e + 255) / 256;
    int vb = (n + 255) / 256;

    // graph preprocessing: degree -> CSR by dst -> dinv
    zero_deg<<<vb, 256>>>(n);
    count_deg<<<eb, 256>>>(dst, e);
    scan_reduce<<<nb, 1024>>>(n);
    scan_bsums<<<1, 32>>>(nb, n);
    scan_final<<<nb, 1024>>>(n);
    fill_csr<<<eb, 256>>>(src, dst, e);
    compute_dinv<<<vb, 256>>>(n);

    int lb = (n + 127) / 128;
    int ab = ((long)n * 32 + 511) / 512;
    float invn = 1.0f / (float)n;

    // layer 1: x(128) -> 64, then BN stats
    linear_kernel<128, false><<<lb, 128>>>(x, W1, b1, hs, n);
    zero_stats<<<1, 64>>>();
    agg_kernel<0><<<ab, 512>>>(hs, agg, n);
    bn_finalize<<<1, 64>>>(g1, be1, invn);

    // layer 2: (BN+ReLU fused into input read)
    linear_kernel<64, true><<<lb, 128>>>(agg, W2, b2, hs, n);
    zero_stats<<<1, 64>>>();
    agg_kernel<0><<<ab, 512>>>(hs, agg, n);
    bn_finalize<<<1, 64>>>(g2, be2, invn);

    // layer 3: + fused log_softmax into final aggregation
    linear_kernel<64, true><<<lb, 128>>>(agg, W3, b3, hs, n);
    agg_kernel<2><<<ab, 512>>>(hs, out, n);
}